// round 8
// baseline (speedup 1.0000x reference)
#include <cuda_runtime.h>
#include <cuda_bf16.h>
#include <cstdint>

#define BATCH 8
#define CDIM  256
#define NTOK  4096

typedef unsigned int u32;

// Scratch (allocation-free rule)
__device__ float          g_q[BATCH * NTOK * 32];    // [b][n][32] tf32-rounded
__device__ float          g_k[BATCH * NTOK * 32];    // [b][n][32] tf32-rounded
__device__ __nv_bfloat16  g_v[(size_t)BATCH * NTOK * CDIM];  // [b][n][256] bf16

__device__ __forceinline__ u32 smem_u32(const void* p) {
    u32 a;
    asm("{ .reg .u64 t; cvta.to.shared.u64 t, %1; cvt.u32.u64 %0, t; }" : "=r"(a) : "l"(p));
    return a;
}
__device__ __forceinline__ float f2tf32f(float x) {
    u32 u; asm("cvt.rna.tf32.f32 %0, %1;" : "=r"(u) : "f"(x));
    return __uint_as_float(u);
}
__device__ __forceinline__ u32 f2tf32u(float x) {
    u32 u; asm("cvt.rna.tf32.f32 %0, %1;" : "=r"(u) : "f"(x));
    return u;
}

#define CP16(dst, src) \
    asm volatile("cp.async.cg.shared.global [%0], [%1], 16;" :: "r"(dst), "l"(src))
#define CP_COMMIT() asm volatile("cp.async.commit_group;" ::: "memory")
#define CP_WAIT(n)  asm volatile("cp.async.wait_group %0;" :: "n"(n) : "memory")

// ---------------------------------------------------------------------------
// Kernel 1: tensor-core QKV projection (tf32 m16n8k8). Unchanged from r4.
// ---------------------------------------------------------------------------
#define QW_STR 36
#define QX_STR 260
#define Q_BUF  (64 * QW_STR * 4 + 32 * QX_STR * 4)   // 42496
#define Q_SMEM (2 * Q_BUF)                            // 84992

__global__ __launch_bounds__(256, 2) void qkv_kernel(
    const float* __restrict__ x,
    const float* __restrict__ Wq, const float* __restrict__ bq,
    const float* __restrict__ Wk, const float* __restrict__ bk,
    const float* __restrict__ Wv, const float* __restrict__ bv)
{
    extern __shared__ __align__(16) char qsm[];
    const int b      = blockIdx.z;
    const int o_base = blockIdx.y * 64;
    const int n_base = blockIdx.x * 256;
    const int tid    = threadIdx.x;
    const int w      = tid >> 5, lane = tid & 31;
    const int grp    = lane >> 2, tig = lane & 3;
    const int wo     = w & 3, wn = w >> 2;
    const float* xb  = x + (size_t)b * CDIM * NTOK;
    const u32 sbase  = smem_u32(qsm);

    const float* wrowp[2];
    int wcol[2];
    int wdst[2];
#pragma unroll
    for (int u = 0; u < 2; ++u) {
        const int idx = tid + u * 256;
        const int row = idx >> 3;
        const int og  = o_base + row;
        wrowp[u] = (og < 32) ? (Wq + (size_t)og * CDIM)
                 : ((og < 64) ? (Wk + (size_t)(og - 32) * CDIM)
                              : (Wv + (size_t)(og - 64) * CDIM));
        wcol[u]  = (idx & 7) * 4;
        wdst[u]  = row * (QW_STR * 4) + (idx & 7) * 16;
    }

    float acc[16][4];
#pragma unroll
    for (int nt = 0; nt < 16; ++nt)
#pragma unroll
        for (int q = 0; q < 4; ++q) acc[nt][q] = 0.0f;

#define QKV_ISSUE(s, sel) do {                                                   \
        const u32 wb = sbase + (sel) * Q_BUF;                                    \
        _Pragma("unroll")                                                        \
        for (int u = 0; u < 2; ++u)                                              \
            CP16(wb + wdst[u], wrowp[u] + (s) * 32 + wcol[u]);                   \
        const u32 xs = wb + 64 * QW_STR * 4;                                     \
        _Pragma("unroll")                                                        \
        for (int u = 0; u < 8; ++u) {                                            \
            const int idx = tid + u * 256;                                       \
            const int cr = idx >> 6, nc = (idx & 63) * 4;                        \
            CP16(xs + cr * (QX_STR * 4) + nc * 4,                                \
                 xb + (size_t)((s) * 32 + cr) * NTOK + n_base + nc);             \
        }                                                                        \
    } while (0)

    QKV_ISSUE(0, 0); CP_COMMIT();

#pragma unroll 1
    for (int s = 0; s < 8; ++s) {
        if (s < 7) { QKV_ISSUE(s + 1, (s + 1) & 1); CP_COMMIT(); CP_WAIT(1); }
        else       { CP_WAIT(0); }
        __syncthreads();
        const float* sW = (const float*)(qsm + (s & 1) * Q_BUF);
        const float* sX = sW + 64 * QW_STR;
#pragma unroll
        for (int ks = 0; ks < 4; ++ks) {
            const int c = ks * 8 + tig;
            u32 a0 = f2tf32u(sW[(wo * 16 + grp) * QW_STR + c]);
            u32 a1 = f2tf32u(sW[(wo * 16 + grp + 8) * QW_STR + c]);
            u32 a2 = f2tf32u(sW[(wo * 16 + grp) * QW_STR + c + 4]);
            u32 a3 = f2tf32u(sW[(wo * 16 + grp + 8) * QW_STR + c + 4]);
#pragma unroll
            for (int nt = 0; nt < 16; ++nt) {
                const int n = wn * 128 + nt * 8 + grp;
                const u32 b0 = __float_as_uint(sX[(ks * 8 + tig) * QX_STR + n]);
                const u32 b1 = __float_as_uint(sX[(ks * 8 + tig + 4) * QX_STR + n]);
                asm volatile(
                    "mma.sync.aligned.m16n8k8.row.col.f32.tf32.tf32.f32 "
                    "{%0,%1,%2,%3}, {%4,%5,%6,%7}, {%8,%9}, {%0,%1,%2,%3};"
                    : "+f"(acc[nt][0]), "+f"(acc[nt][1]), "+f"(acc[nt][2]), "+f"(acc[nt][3])
                    : "r"(a0), "r"(a1), "r"(a2), "r"(a3), "r"(b0), "r"(b1));
            }
        }
        __syncthreads();
    }

    {
        const int o0 = o_base + wo * 16 + grp;
        const int o1 = o0 + 8;
        const float bias0 = (o0 < 32) ? bq[o0] : ((o0 < 64) ? bk[o0 - 32] : bv[o0 - 64]);
        const float bias1 = (o1 < 32) ? bq[o1] : ((o1 < 64) ? bk[o1 - 32] : bv[o1 - 64]);
#pragma unroll
        for (int nt = 0; nt < 16; ++nt) {
            acc[nt][0] += bias0; acc[nt][1] += bias0;
            acc[nt][2] += bias1; acc[nt][3] += bias1;
        }
    }

    float* stage = (float*)qsm;
    __syncthreads();
#pragma unroll
    for (int nt = 0; nt < 16; ++nt) {
        const int n = wn * 128 + nt * 8 + 2 * tig;
        const int o0 = wo * 16 + grp;
        stage[n * 68 + o0]           = acc[nt][0];
        stage[(n + 1) * 68 + o0]     = acc[nt][1];
        stage[n * 68 + o0 + 8]       = acc[nt][2];
        stage[(n + 1) * 68 + o0 + 8] = acc[nt][3];
    }
    __syncthreads();

    {
        const int n = tid;
        const float* sr = stage + n * 68;
        if (o_base == 0) {
            float* dq = g_q + ((size_t)b * NTOK + n_base + n) * 32;
            float* dk = g_k + ((size_t)b * NTOK + n_base + n) * 32;
#pragma unroll
            for (int c4 = 0; c4 < 8; ++c4) {
                float4 v = *(const float4*)(sr + c4 * 4);
                *(float4*)(dq + c4 * 4) = make_float4(f2tf32f(v.x), f2tf32f(v.y),
                                                      f2tf32f(v.z), f2tf32f(v.w));
                float4 u = *(const float4*)(sr + 32 + c4 * 4);
                *(float4*)(dk + c4 * 4) = make_float4(f2tf32f(u.x), f2tf32f(u.y),
                                                      f2tf32f(u.z), f2tf32f(u.w));
            }
        } else {
            __nv_bfloat16* dv = g_v + ((size_t)b * NTOK + n_base + n) * CDIM + (o_base - 64);
#pragma unroll
            for (int c4 = 0; c4 < 16; ++c4) {
                float4 v = *(const float4*)(sr + c4 * 4);
                u32 p01, p23;
                asm("cvt.rn.bf16x2.f32 %0, %1, %2;" : "=r"(p01) : "f"(v.y), "f"(v.x));
                asm("cvt.rn.bf16x2.f32 %0, %1, %2;" : "=r"(p23) : "f"(v.w), "f"(v.z));
                *(uint2*)(dv + c4 * 4) = make_uint2(p01, p23);
            }
        }
    }
}

// ---------------------------------------------------------------------------
// Kernel 2: warp-MMA flash attention, 32-row x 128-col warp tiles.
// 256 threads = 8 warps: wr = w>>1 (row group of 32), wc = w&1 (col half).
// Per j-tile (64 keys):
//   S: warp computes S[32 rows][j-half wc] (tf32), exp, partial l,
//      packs P bf16 -> smem (shared across col-halves).
//   O: A-frags from P smem (ldmatrix), B V-frags per col-half; kj-outer loop
//      so each B frag feeds 2 row-tiles and acc chains are 32 apart.
// Triple-buffered cp.async ring for K/V.
// ---------------------------------------------------------------------------
#define KSTR 36        // K smem row stride (floats)
#define VSTR 264       // V smem row stride (bf16)
#define A_BUF 43008    // 64*36*4 + 64*264*2
#define OFF_P  (3 * A_BUF)               // 129024
#define OFF_SL (OFF_P + 128 * 72 * 2)    // 147456
#define A_SMEM (OFF_SL + 256 * 4)        // 148480

__global__ __launch_bounds__(256, 1) void attn_kernel(
    const float* __restrict__ x,
    const float* __restrict__ gamma,
    float* __restrict__ out)
{
    extern __shared__ __align__(16) char smem[];
    const int tid  = threadIdx.x;
    const int w    = tid >> 5;
    const int lane = tid & 31;
    const int grp  = lane >> 2;
    const int tig  = lane & 3;
    const int wr   = w >> 1;    // row group (32 rows)
    const int wc   = w & 1;     // col half / j half
    const int b    = blockIdx.y;
    const int ibase = blockIdx.x * 128;
    const u32 sbase = smem_u32(smem);

#define ATTN_ISSUE(t, sel) do {                                                  \
        const u32 kb_ = sbase + (u32)(sel) * A_BUF;                              \
        const float4* gk = (const float4*)(g_k + ((size_t)b * NTOK + (t) * 64) * 32); \
        _Pragma("unroll")                                                        \
        for (int u = 0; u < 2; ++u) {                                            \
            const int idx = tid + u * 256;                                       \
            CP16(kb_ + (idx >> 3) * (KSTR * 4) + (idx & 7) * 16, gk + idx);      \
        }                                                                        \
        const u32 vb_ = kb_ + 64 * KSTR * 4;                                     \
        const uint4* gv = (const uint4*)(g_v + ((size_t)b * NTOK + (t) * 64) * CDIM); \
        _Pragma("unroll")                                                        \
        for (int u = 0; u < 8; ++u) {                                            \
            const int idx = tid + u * 256;                                       \
            CP16(vb_ + (idx >> 5) * (VSTR * 2) + (idx & 31) * 16, gv + idx);     \
        }                                                                        \
    } while (0)

    ATTN_ISSUE(0, 0); CP_COMMIT();
    ATTN_ISSUE(1, 1); CP_COMMIT();

    // ---- Q A-fragments (tf32 m16n8k8): rows ibase + wr*32 + rt*16 + {grp,grp+8}
    u32 qa[2][4][4];
    {
        const float* Qb = g_q + ((size_t)b * NTOK + ibase + wr * 32) * 32;
#pragma unroll
        for (int rt = 0; rt < 2; ++rt)
#pragma unroll
            for (int ks = 0; ks < 4; ++ks) {
                const int c = ks * 8 + tig;
                qa[rt][ks][0] = __float_as_uint(Qb[(rt * 16 + grp) * 32 + c]);
                qa[rt][ks][1] = __float_as_uint(Qb[(rt * 16 + grp + 8) * 32 + c]);
                qa[rt][ks][2] = __float_as_uint(Qb[(rt * 16 + grp) * 32 + c + 4]);
                qa[rt][ks][3] = __float_as_uint(Qb[(rt * 16 + grp + 8) * 32 + c + 4]);
            }
    }

    float acc[2][16][4];   // [row tile][n8 tile within 128 cols][frag]
#pragma unroll
    for (int rt = 0; rt < 2; ++rt)
#pragma unroll
        for (int nt = 0; nt < 16; ++nt)
#pragma unroll
            for (int q = 0; q < 4; ++q) acc[rt][nt][q] = 0.0f;
    float lsum[2][2] = {{0.f, 0.f}, {0.f, 0.f}};

    u32* sP = (u32*)(smem + OFF_P);
    const int prow_base = (wr * 32 + grp) * 36 + wc * 16;   // u32 index; +rt*576, +288 for row+8
    // P A-frag ldmatrix address (non-trans, m16k16): +rt*2304, +kj*32
    const u32 paddr0 = sbase + OFF_P
                     + (u32)((wr * 32 + (lane & 15)) * 144 + ((lane >> 4) * 16));
    // V B-frag ldmatrix address (trans): +kj*16*528, +cb*32, + buffer offset
    const u32 vfoff = (u32)((lane & 15) * (VSTR * 2) + ((lane >> 4) * 16) + wc * 256);

#pragma unroll 1
    for (int t = 0; t < 64; ++t) {
        if (t < 63) CP_WAIT(1); else CP_WAIT(0);
        __syncthreads();
        if (t < 62) { ATTN_ISSUE(t + 2, (t + 2) % 3); CP_COMMIT(); }

        const int sel = t % 3;
        const float* Ks = (const float*)(smem + sel * A_BUF);

        // ---- S phase: S[32 rows][j in wc*32 .. +31]  (tf32), exp, pack -> sP
#pragma unroll
        for (int rt = 0; rt < 2; ++rt) {
#pragma unroll
            for (int ntl = 0; ntl < 4; ++ntl) {
                const int ntg = wc * 4 + ntl;
                float s0 = 0.f, s1 = 0.f, s2 = 0.f, s3 = 0.f;
#pragma unroll
                for (int ks = 0; ks < 4; ++ks) {
                    const u32 b0 = __float_as_uint(Ks[(ntg * 8 + grp) * KSTR + ks * 8 + tig]);
                    const u32 b1 = __float_as_uint(Ks[(ntg * 8 + grp) * KSTR + ks * 8 + 4 + tig]);
                    asm volatile(
                        "mma.sync.aligned.m16n8k8.row.col.f32.tf32.tf32.f32 "
                        "{%0,%1,%2,%3}, {%4,%5,%6,%7}, {%8,%9}, {%0,%1,%2,%3};"
                        : "+f"(s0), "+f"(s1), "+f"(s2), "+f"(s3)
                        : "r"(qa[rt][ks][0]), "r"(qa[rt][ks][1]),
                          "r"(qa[rt][ks][2]), "r"(qa[rt][ks][3]),
                          "r"(b0), "r"(b1));
                }
                s0 = __expf(s0); s1 = __expf(s1); s2 = __expf(s2); s3 = __expf(s3);
                lsum[rt][0] += s0 + s1;
                lsum[rt][1] += s2 + s3;
                u32 k0, k1;
                asm("cvt.rn.bf16x2.f32 %0, %1, %2;" : "=r"(k0) : "f"(s1), "f"(s0));
                asm("cvt.rn.bf16x2.f32 %0, %1, %2;" : "=r"(k1) : "f"(s3), "f"(s2));
                const int pi = prow_base + rt * 576 + ntl * 4 + tig;
                sP[pi]       = k0;
                sP[pi + 288] = k1;
            }
        }
        __syncthreads();   // P tile complete

        // ---- load P A-fragments (rows wr*32..+31, k = 64)
        u32 pa[2][4][4];
#pragma unroll
        for (int rt = 0; rt < 2; ++rt)
#pragma unroll
            for (int kj = 0; kj < 4; ++kj) {
                asm volatile(
                    "ldmatrix.sync.aligned.m8n8.x4.shared.b16 {%0,%1,%2,%3}, [%4];"
                    : "=r"(pa[rt][kj][0]), "=r"(pa[rt][kj][1]),
                      "=r"(pa[rt][kj][2]), "=r"(pa[rt][kj][3])
                    : "r"(paddr0 + (u32)(rt * 2304 + kj * 32)));
            }

        // ---- O += P * V : kj-outer, hoisted B frags, 32-independent HMMA runs
        const u32 vb = sbase + (u32)sel * A_BUF + 64 * KSTR * 4 + vfoff;
#pragma unroll
        for (int kj = 0; kj < 4; ++kj) {
            u32 bf[8][4];
#pragma unroll
            for (int cb = 0; cb < 8; ++cb) {
                asm volatile(
                    "ldmatrix.sync.aligned.m8n8.x4.trans.shared.b16 {%0,%1,%2,%3}, [%4];"
                    : "=r"(bf[cb][0]), "=r"(bf[cb][1]), "=r"(bf[cb][2]), "=r"(bf[cb][3])
                    : "r"(vb + (u32)(kj * 16 * (VSTR * 2) + cb * 32)));
            }
#pragma unroll
            for (int cb = 0; cb < 8; ++cb) {
#pragma unroll
                for (int rt = 0; rt < 2; ++rt) {
                    asm volatile(
                        "mma.sync.aligned.m16n8k16.row.col.f32.bf16.bf16.f32 "
                        "{%0,%1,%2,%3}, {%4,%5,%6,%7}, {%8,%9}, {%0,%1,%2,%3};"
                        : "+f"(acc[rt][cb*2][0]), "+f"(acc[rt][cb*2][1]),
                          "+f"(acc[rt][cb*2][2]), "+f"(acc[rt][cb*2][3])
                        : "r"(pa[rt][kj][0]), "r"(pa[rt][kj][1]),
                          "r"(pa[rt][kj][2]), "r"(pa[rt][kj][3]),
                          "r"(bf[cb][0]), "r"(bf[cb][1]));
                    asm volatile(
                        "mma.sync.aligned.m16n8k16.row.col.f32.bf16.bf16.f32 "
                        "{%0,%1,%2,%3}, {%4,%5,%6,%7}, {%8,%9}, {%0,%1,%2,%3};"
                        : "+f"(acc[rt][cb*2+1][0]), "+f"(acc[rt][cb*2+1][1]),
                          "+f"(acc[rt][cb*2+1][2]), "+f"(acc[rt][cb*2+1][3])
                        : "r"(pa[rt][kj][0]), "r"(pa[rt][kj][1]),
                          "r"(pa[rt][kj][2]), "r"(pa[rt][kj][3]),
                          "r"(bf[cb][2]), "r"(bf[cb][3]));
                }
            }
        }
    }
    __syncthreads();

    // ---- combine partial row sums (two j-halves) via smem
    float* sL = (float*)(smem + OFF_SL);
#pragma unroll
    for (int rt = 0; rt < 2; ++rt)
#pragma unroll
        for (int h = 0; h < 2; ++h) {
            lsum[rt][h] += __shfl_xor_sync(0xFFFFFFFFu, lsum[rt][h], 1);
            lsum[rt][h] += __shfl_xor_sync(0xFFFFFFFFu, lsum[rt][h], 2);
        }
    if (tig == 0) {
#pragma unroll
        for (int rt = 0; rt < 2; ++rt) {
            sL[wc * 128 + wr * 32 + rt * 16 + grp]     = lsum[rt][0];
            sL[wc * 128 + wr * 32 + rt * 16 + grp + 8] = lsum[rt][1];
        }
    }
    __syncthreads();
    const float gval = gamma[0];
    float invl[2][2];
#pragma unroll
    for (int rt = 0; rt < 2; ++rt) {
        const int r0 = wr * 32 + rt * 16 + grp;
        invl[rt][0] = gval / (sL[r0] + sL[128 + r0]);
        invl[rt][1] = gval / (sL[r0 + 8] + sL[128 + r0 + 8]);
    }
    __syncthreads();

    // ---- epilogue: 4 chunks of 64 cols x 128 i, staged via smem
    float* stage = (float*)smem;
#pragma unroll 1
    for (int cc = 0; cc < 4; ++cc) {
        if (wc == (cc >> 1)) {
            const int half = cc & 1;
#pragma unroll
            for (int rt = 0; rt < 2; ++rt)
#pragma unroll
                for (int ntl = 0; ntl < 8; ++ntl) {
                    const int nt = half * 8 + ntl;
                    const int c0 = ntl * 8 + 2 * tig;
                    const int i0 = wr * 32 + rt * 16 + grp;
                    stage[c0 * 132 + i0]           = acc[rt][nt][0] * invl[rt][0];
                    stage[(c0 + 1) * 132 + i0]     = acc[rt][nt][1] * invl[rt][0];
                    stage[c0 * 132 + i0 + 8]       = acc[rt][nt][2] * invl[rt][1];
                    stage[(c0 + 1) * 132 + i0 + 8] = acc[rt][nt][3] * invl[rt][1];
                }
        }
        __syncthreads();
        {
            const int cl = tid >> 2;
            const int cg = cc * 64 + cl;
            const int ii0 = (tid & 3) * 32;
            const size_t row = ((size_t)b * CDIM + cg) * NTOK + ibase;
#pragma unroll
            for (int u = 0; u < 8; ++u) {
                const int i = ii0 + u * 4;
                const float4 sv = *(const float4*)&stage[cl * 132 + i];
                const float4 xv = *(const float4*)(x + row + i);
                *(float4*)(out + row + i) =
                    make_float4(sv.x + xv.x, sv.y + xv.y, sv.z + xv.z, sv.w + xv.w);
            }
        }
        __syncthreads();
    }
}

// ---------------------------------------------------------------------------
extern "C" void kernel_launch(void* const* d_in, const int* in_sizes, int n_in,
                              void* d_out, int out_size)
{
    const float* x     = (const float*)d_in[0];
    const float* Wq    = (const float*)d_in[1];
    const float* bq    = (const float*)d_in[2];
    const float* Wk    = (const float*)d_in[3];
    const float* bk    = (const float*)d_in[4];
    const float* Wv    = (const float*)d_in[5];
    const float* bv    = (const float*)d_in[6];
    const float* gamma = (const float*)d_in[7];
    float* out = (float*)d_out;

    cudaFuncSetAttribute(qkv_kernel, cudaFuncAttributeMaxDynamicSharedMemorySize, Q_SMEM);
    cudaFuncSetAttribute(attn_kernel, cudaFuncAttributeMaxDynamicSharedMemorySize, A_SMEM);

    qkv_kernel<<<dim3(NTOK / 256, 5, BATCH), 256, Q_SMEM>>>(x, Wq, bq, Wk, bk, Wv, bv);
    attn_kernel<<<dim3(NTOK / 128, BATCH), 256, A_SMEM>>>(x, gamma, out);
}

// round 11
// speedup vs baseline: 2.4008x; 2.4008x over previous
#include <cuda_runtime.h>
#include <cuda_bf16.h>
#include <cstdint>

#define BATCH 8
#define CDIM  256
#define NTOK  4096

typedef unsigned int u32;

// Scratch (allocation-free rule)
__device__ float          g_q[BATCH * NTOK * 32];    // [b][n][32] tf32-rounded
__device__ float          g_k[BATCH * NTOK * 32];    // [b][n][32] tf32-rounded
__device__ __nv_bfloat16  g_v[(size_t)BATCH * NTOK * CDIM];  // [b][n][256] bf16

__device__ __forceinline__ u32 smem_u32(const void* p) {
    u32 a;
    asm("{ .reg .u64 t; cvta.to.shared.u64 t, %1; cvt.u32.u64 %0, t; }" : "=r"(a) : "l"(p));
    return a;
}
__device__ __forceinline__ float f2tf32f(float x) {
    u32 u; asm("cvt.rna.tf32.f32 %0, %1;" : "=r"(u) : "f"(x));
    return __uint_as_float(u);
}
__device__ __forceinline__ u32 f2tf32u(float x) {
    u32 u; asm("cvt.rna.tf32.f32 %0, %1;" : "=r"(u) : "f"(x));
    return u;
}

#define CP16(dst, src) \
    asm volatile("cp.async.cg.shared.global [%0], [%1], 16;" :: "r"(dst), "l"(src))
#define CP_COMMIT() asm volatile("cp.async.commit_group;" ::: "memory")
#define CP_WAIT(n)  asm volatile("cp.async.wait_group %0;" :: "n"(n) : "memory")

// ---------------------------------------------------------------------------
// Kernel 1: tensor-core QKV projection (tf32 m16n8k8). Unchanged from r4.
// ---------------------------------------------------------------------------
#define QW_STR 36
#define QX_STR 260
#define Q_BUF  (64 * QW_STR * 4 + 32 * QX_STR * 4)   // 42496
#define Q_SMEM (2 * Q_BUF)                            // 84992

__global__ __launch_bounds__(256, 2) void qkv_kernel(
    const float* __restrict__ x,
    const float* __restrict__ Wq, const float* __restrict__ bq,
    const float* __restrict__ Wk, const float* __restrict__ bk,
    const float* __restrict__ Wv, const float* __restrict__ bv)
{
    extern __shared__ __align__(16) char qsm[];
    const int b      = blockIdx.z;
    const int o_base = blockIdx.y * 64;
    const int n_base = blockIdx.x * 256;
    const int tid    = threadIdx.x;
    const int w      = tid >> 5, lane = tid & 31;
    const int grp    = lane >> 2, tig = lane & 3;
    const int wo     = w & 3, wn = w >> 2;
    const float* xb  = x + (size_t)b * CDIM * NTOK;
    const u32 sbase  = smem_u32(qsm);

    const float* wrowp[2];
    int wcol[2];
    int wdst[2];
#pragma unroll
    for (int u = 0; u < 2; ++u) {
        const int idx = tid + u * 256;
        const int row = idx >> 3;
        const int og  = o_base + row;
        wrowp[u] = (og < 32) ? (Wq + (size_t)og * CDIM)
                 : ((og < 64) ? (Wk + (size_t)(og - 32) * CDIM)
                              : (Wv + (size_t)(og - 64) * CDIM));
        wcol[u]  = (idx & 7) * 4;
        wdst[u]  = row * (QW_STR * 4) + (idx & 7) * 16;
    }

    float acc[16][4];
#pragma unroll
    for (int nt = 0; nt < 16; ++nt)
#pragma unroll
        for (int q = 0; q < 4; ++q) acc[nt][q] = 0.0f;

#define QKV_ISSUE(s, sel) do {                                                   \
        const u32 wb = sbase + (sel) * Q_BUF;                                    \
        _Pragma("unroll")                                                        \
        for (int u = 0; u < 2; ++u)                                              \
            CP16(wb + wdst[u], wrowp[u] + (s) * 32 + wcol[u]);                   \
        const u32 xs = wb + 64 * QW_STR * 4;                                     \
        _Pragma("unroll")                                                        \
        for (int u = 0; u < 8; ++u) {                                            \
            const int idx = tid + u * 256;                                       \
            const int cr = idx >> 6, nc = (idx & 63) * 4;                        \
            CP16(xs + cr * (QX_STR * 4) + nc * 4,                                \
                 xb + (size_t)((s) * 32 + cr) * NTOK + n_base + nc);             \
        }                                                                        \
    } while (0)

    QKV_ISSUE(0, 0); CP_COMMIT();

#pragma unroll 1
    for (int s = 0; s < 8; ++s) {
        if (s < 7) { QKV_ISSUE(s + 1, (s + 1) & 1); CP_COMMIT(); CP_WAIT(1); }
        else       { CP_WAIT(0); }
        __syncthreads();
        const float* sW = (const float*)(qsm + (s & 1) * Q_BUF);
        const float* sX = sW + 64 * QW_STR;
#pragma unroll
        for (int ks = 0; ks < 4; ++ks) {
            const int c = ks * 8 + tig;
            u32 a0 = f2tf32u(sW[(wo * 16 + grp) * QW_STR + c]);
            u32 a1 = f2tf32u(sW[(wo * 16 + grp + 8) * QW_STR + c]);
            u32 a2 = f2tf32u(sW[(wo * 16 + grp) * QW_STR + c + 4]);
            u32 a3 = f2tf32u(sW[(wo * 16 + grp + 8) * QW_STR + c + 4]);
#pragma unroll
            for (int nt = 0; nt < 16; ++nt) {
                const int n = wn * 128 + nt * 8 + grp;
                const u32 b0 = __float_as_uint(sX[(ks * 8 + tig) * QX_STR + n]);
                const u32 b1 = __float_as_uint(sX[(ks * 8 + tig + 4) * QX_STR + n]);
                asm volatile(
                    "mma.sync.aligned.m16n8k8.row.col.f32.tf32.tf32.f32 "
                    "{%0,%1,%2,%3}, {%4,%5,%6,%7}, {%8,%9}, {%0,%1,%2,%3};"
                    : "+f"(acc[nt][0]), "+f"(acc[nt][1]), "+f"(acc[nt][2]), "+f"(acc[nt][3])
                    : "r"(a0), "r"(a1), "r"(a2), "r"(a3), "r"(b0), "r"(b1));
            }
        }
        __syncthreads();
    }

    {
        const int o0 = o_base + wo * 16 + grp;
        const int o1 = o0 + 8;
        const float bias0 = (o0 < 32) ? bq[o0] : ((o0 < 64) ? bk[o0 - 32] : bv[o0 - 64]);
        const float bias1 = (o1 < 32) ? bq[o1] : ((o1 < 64) ? bk[o1 - 32] : bv[o1 - 64]);
#pragma unroll
        for (int nt = 0; nt < 16; ++nt) {
            acc[nt][0] += bias0; acc[nt][1] += bias0;
            acc[nt][2] += bias1; acc[nt][3] += bias1;
        }
    }

    float* stage = (float*)qsm;
    __syncthreads();
#pragma unroll
    for (int nt = 0; nt < 16; ++nt) {
        const int n = wn * 128 + nt * 8 + 2 * tig;
        const int o0 = wo * 16 + grp;
        stage[n * 68 + o0]           = acc[nt][0];
        stage[(n + 1) * 68 + o0]     = acc[nt][1];
        stage[n * 68 + o0 + 8]       = acc[nt][2];
        stage[(n + 1) * 68 + o0 + 8] = acc[nt][3];
    }
    __syncthreads();

    {
        const int n = tid;
        const float* sr = stage + n * 68;
        if (o_base == 0) {
            float* dq = g_q + ((size_t)b * NTOK + n_base + n) * 32;
            float* dk = g_k + ((size_t)b * NTOK + n_base + n) * 32;
#pragma unroll
            for (int c4 = 0; c4 < 8; ++c4) {
                float4 v = *(const float4*)(sr + c4 * 4);
                *(float4*)(dq + c4 * 4) = make_float4(f2tf32f(v.x), f2tf32f(v.y),
                                                      f2tf32f(v.z), f2tf32f(v.w));
                float4 u = *(const float4*)(sr + 32 + c4 * 4);
                *(float4*)(dk + c4 * 4) = make_float4(f2tf32f(u.x), f2tf32f(u.y),
                                                      f2tf32f(u.z), f2tf32f(u.w));
            }
        } else {
            __nv_bfloat16* dv = g_v + ((size_t)b * NTOK + n_base + n) * CDIM + (o_base - 64);
#pragma unroll
            for (int c4 = 0; c4 < 16; ++c4) {
                float4 v = *(const float4*)(sr + c4 * 4);
                u32 p01, p23;
                asm("cvt.rn.bf16x2.f32 %0, %1, %2;" : "=r"(p01) : "f"(v.y), "f"(v.x));
                asm("cvt.rn.bf16x2.f32 %0, %1, %2;" : "=r"(p23) : "f"(v.w), "f"(v.z));
                *(uint2*)(dv + c4 * 4) = make_uint2(p01, p23);
            }
        }
    }
}

// ---------------------------------------------------------------------------
// Kernel 2: warp-MMA flash attention, 512 thr / 16 warps, lagged pipeline.
// Warp (wr = w&7: 16-row group, wc = w>>3: half).
//   iter t: S(t) for rows wr*16, keys j-half wc -> P smem buf (t&1);
//           O(t-1): rows wr*16, cols wc*128, P from buf ((t-1)&1) full-row
//           A-frags via ldmatrix, V from KV ring buf ((t-1)&3).
// One __syncthreads per iter; 4-deep KV cp.async ring; regs ~110 (no spill).
// ---------------------------------------------------------------------------
#define KSTR 36        // K smem row stride (floats)
#define VSTR 264       // V smem row stride (bf16)
#define PSTR 72        // P smem row stride (bf16)
#define A_BUF 43008    // 64*36*4 + 64*264*2
#define PB_SZ (128 * PSTR * 2)           // 18432
#define OFF_P  (4 * A_BUF)               // 172032
#define OFF_SL (OFF_P + 2 * PB_SZ)       // 208896
#define A_SMEM (OFF_SL + 256 * 4)        // 209920

__global__ __launch_bounds__(512, 1) void attn_kernel(
    const float* __restrict__ x,
    const float* __restrict__ gamma,
    float* __restrict__ out)
{
    extern __shared__ __align__(16) char smem[];
    const int tid  = threadIdx.x;
    const int w    = tid >> 5;
    const int lane = tid & 31;
    const int grp  = lane >> 2;
    const int tig  = lane & 3;
    const int wr   = w & 7;     // row group (16 rows)
    const int wc   = w >> 3;    // half
    const int b    = blockIdx.y;
    const int ibase = blockIdx.x * 128;
    const u32 sbase = smem_u32(smem);

#define ATTN_ISSUE(t, sel) do {                                                  \
        const u32 kb_ = sbase + (u32)(sel) * A_BUF;                              \
        const float4* gk = (const float4*)(g_k + ((size_t)b * NTOK + (t) * 64) * 32); \
        CP16(kb_ + (tid >> 3) * (KSTR * 4) + (tid & 7) * 16, gk + tid);          \
        const u32 vb_ = kb_ + 64 * KSTR * 4;                                     \
        const uint4* gv = (const uint4*)(g_v + ((size_t)b * NTOK + (t) * 64) * CDIM); \
        _Pragma("unroll")                                                        \
        for (int u = 0; u < 4; ++u) {                                            \
            const int idx = tid + u * 512;                                       \
            CP16(vb_ + (idx >> 5) * (VSTR * 2) + (idx & 31) * 16, gv + idx);     \
        }                                                                        \
    } while (0)

    ATTN_ISSUE(0, 0); CP_COMMIT();
    ATTN_ISSUE(1, 1); CP_COMMIT();

    // ---- Q A-fragments (tf32 m16n8k8): rows ibase + wr*16 + {grp, grp+8}
    u32 qa[4][4];
    {
        const float* Qb = g_q + ((size_t)b * NTOK + ibase + wr * 16) * 32;
#pragma unroll
        for (int ks = 0; ks < 4; ++ks) {
            const int c = ks * 8 + tig;
            qa[ks][0] = __float_as_uint(Qb[grp * 32 + c]);
            qa[ks][1] = __float_as_uint(Qb[(grp + 8) * 32 + c]);
            qa[ks][2] = __float_as_uint(Qb[grp * 32 + c + 4]);
            qa[ks][3] = __float_as_uint(Qb[(grp + 8) * 32 + c + 4]);
        }
    }

    float acc[16][4];   // O accum: cols wc*128 .. +127
#pragma unroll
    for (int i = 0; i < 16; ++i)
#pragma unroll
        for (int q = 0; q < 4; ++q) acc[i][q] = 0.0f;
    float l0 = 0.0f, l1 = 0.0f;

    // P smem write indexing (u32 view, row stride 36): row wr*16+grp (+8),
    // col wc*16 + ntl*4 + tig
    const int prow0 = (wr * 16 + grp) * (PSTR / 2) + wc * 16;
    // P A-frag read (non-trans m8n8.x4): rows wr*16 + (lane&15), +kj*32 B
    const u32 paoff = (u32)(((wr * 16 + (lane & 15)) * PSTR + ((lane >> 4) & 1) * 8) * 2);
    // V B-frag (trans): col half wc
    const u32 vfoff = (u32)(((lane & 15) * VSTR + ((lane >> 4) * 8) + wc * 128) * 2);

#pragma unroll 1
    for (int t = 0; t <= 64; ++t) {
        if (t < 63)       CP_WAIT(1);
        else if (t == 63) CP_WAIT(0);
        __syncthreads();
        if (t + 2 < 64) { ATTN_ISSUE(t + 2, (t + 2) & 3); CP_COMMIT(); }

        // ---- S(t): rows wr*16, keys j-half wc (4 n8-blocks), pack -> P[t&1]
        if (t < 64) {
            const float* Ks = (const float*)(smem + (t & 3) * A_BUF);
            u32* sP = (u32*)(smem + OFF_P + (t & 1) * PB_SZ);
#pragma unroll
            for (int ntl = 0; ntl < 4; ++ntl) {
                const int ntg = wc * 4 + ntl;
                float s0 = 0.f, s1 = 0.f, s2 = 0.f, s3 = 0.f;
#pragma unroll
                for (int ks = 0; ks < 4; ++ks) {
                    const u32 b0 = __float_as_uint(Ks[(ntg * 8 + grp) * KSTR + ks * 8 + tig]);
                    const u32 b1 = __float_as_uint(Ks[(ntg * 8 + grp) * KSTR + ks * 8 + 4 + tig]);
                    asm volatile(
                        "mma.sync.aligned.m16n8k8.row.col.f32.tf32.tf32.f32 "
                        "{%0,%1,%2,%3}, {%4,%5,%6,%7}, {%8,%9}, {%0,%1,%2,%3};"
                        : "+f"(s0), "+f"(s1), "+f"(s2), "+f"(s3)
                        : "r"(qa[ks][0]), "r"(qa[ks][1]), "r"(qa[ks][2]), "r"(qa[ks][3]),
                          "r"(b0), "r"(b1));
                }
                s0 = __expf(s0); s1 = __expf(s1); s2 = __expf(s2); s3 = __expf(s3);
                l0 += s0 + s1;
                l1 += s2 + s3;
                u32 k0, k1;
                asm("cvt.rn.bf16x2.f32 %0, %1, %2;" : "=r"(k0) : "f"(s1), "f"(s0));
                asm("cvt.rn.bf16x2.f32 %0, %1, %2;" : "=r"(k1) : "f"(s3), "f"(s2));
                const int pi = prow0 + ntl * 4 + tig;
                sP[pi]                  = k0;
                sP[pi + 8 * (PSTR / 2)] = k1;
            }
        }

        // ---- O(t-1): P[(t-1)&1] full row, V ring buf (t-1)&3, cols wc*128..
        if (t > 0) {
            const u32 pabase = sbase + OFF_P + (u32)((t - 1) & 1) * PB_SZ + paoff;
            u32 pa[4][4];
#pragma unroll
            for (int kj = 0; kj < 4; ++kj) {
                asm volatile(
                    "ldmatrix.sync.aligned.m8n8.x4.shared.b16 {%0,%1,%2,%3}, [%4];"
                    : "=r"(pa[kj][0]), "=r"(pa[kj][1]), "=r"(pa[kj][2]), "=r"(pa[kj][3])
                    : "r"(pabase + (u32)(kj * 32)));
            }
            const u32 lmbase = sbase + (u32)((t - 1) & 3) * A_BUF + 64 * KSTR * 4 + vfoff;
#pragma unroll
            for (int cb = 0; cb < 8; ++cb) {
#pragma unroll
                for (int kj = 0; kj < 4; ++kj) {
                    u32 r0, r1, r2, r3;
                    const u32 addr = lmbase + (u32)(kj * 16 * (VSTR * 2) + cb * 32);
                    asm volatile(
                        "ldmatrix.sync.aligned.m8n8.x4.trans.shared.b16 {%0,%1,%2,%3}, [%4];"
                        : "=r"(r0), "=r"(r1), "=r"(r2), "=r"(r3) : "r"(addr));
                    asm volatile(
                        "mma.sync.aligned.m16n8k16.row.col.f32.bf16.bf16.f32 "
                        "{%0,%1,%2,%3}, {%4,%5,%6,%7}, {%8,%9}, {%0,%1,%2,%3};"
                        : "+f"(acc[cb*2][0]), "+f"(acc[cb*2][1]),
                          "+f"(acc[cb*2][2]), "+f"(acc[cb*2][3])
                        : "r"(pa[kj][0]), "r"(pa[kj][1]), "r"(pa[kj][2]), "r"(pa[kj][3]),
                          "r"(r0), "r"(r1));
                    asm volatile(
                        "mma.sync.aligned.m16n8k16.row.col.f32.bf16.bf16.f32 "
                        "{%0,%1,%2,%3}, {%4,%5,%6,%7}, {%8,%9}, {%0,%1,%2,%3};"
                        : "+f"(acc[cb*2+1][0]), "+f"(acc[cb*2+1][1]),
                          "+f"(acc[cb*2+1][2]), "+f"(acc[cb*2+1][3])
                        : "r"(pa[kj][0]), "r"(pa[kj][1]), "r"(pa[kj][2]), "r"(pa[kj][3]),
                          "r"(r2), "r"(r3));
                }
            }
        }
    }
    __syncthreads();

    // ---- combine partial row sums (two j-halves) via smem
    float* sL = (float*)(smem + OFF_SL);
    l0 += __shfl_xor_sync(0xFFFFFFFFu, l0, 1);
    l0 += __shfl_xor_sync(0xFFFFFFFFu, l0, 2);
    l1 += __shfl_xor_sync(0xFFFFFFFFu, l1, 1);
    l1 += __shfl_xor_sync(0xFFFFFFFFu, l1, 2);
    if (tig == 0) {
        sL[wc * 128 + wr * 16 + grp]     = l0;
        sL[wc * 128 + wr * 16 + grp + 8] = l1;
    }
    __syncthreads();
    const float gval = gamma[0];
    const float invl0 = gval / (sL[wr * 16 + grp]     + sL[128 + wr * 16 + grp]);
    const float invl1 = gval / (sL[wr * 16 + grp + 8] + sL[128 + wr * 16 + grp + 8]);
    __syncthreads();

    // ---- epilogue: 4 chunks of 64 cols x 128 i, staged via smem
    float* stage = (float*)smem;
#pragma unroll 1
    for (int cc = 0; cc < 4; ++cc) {
        if (wc == (cc >> 1)) {
            const int half = cc & 1;
#pragma unroll
            for (int nt8 = 0; nt8 < 8; ++nt8) {
                const int a = half * 8 + nt8;
                const int c0 = nt8 * 8 + 2 * tig;
                const int i0 = wr * 16 + grp;
                stage[c0 * 132 + i0]           = acc[a][0] * invl0;
                stage[(c0 + 1) * 132 + i0]     = acc[a][1] * invl0;
                stage[c0 * 132 + i0 + 8]       = acc[a][2] * invl1;
                stage[(c0 + 1) * 132 + i0 + 8] = acc[a][3] * invl1;
            }
        }
        __syncthreads();
        {
            const int cl  = tid >> 3;
            const int cg  = cc * 64 + cl;
            const int ii0 = (tid & 7) * 16;
            const size_t row = ((size_t)b * CDIM + cg) * NTOK + ibase;
#pragma unroll
            for (int u = 0; u < 4; ++u) {
                const int i = ii0 + u * 4;
                const float4 sv = *(const float4*)&stage[cl * 132 + i];
                const float4 xv = *(const float4*)(x + row + i);
                *(float4*)(out + row + i) =
                    make_float4(sv.x + xv.x, sv.y + xv.y, sv.z + xv.z, sv.w + xv.w);
            }
        }
        __syncthreads();
    }
}

// ---------------------------------------------------------------------------
extern "C" void kernel_launch(void* const* d_in, const int* in_sizes, int n_in,
                              void* d_out, int out_size)
{
    const float* x     = (const float*)d_in[0];
    const float* Wq    = (const float*)d_in[1];
    const float* bq    = (const float*)d_in[2];
    const float* Wk    = (const float*)d_in[3];
    const float* bk    = (const float*)d_in[4];
    const float* Wv    = (const float*)d_in[5];
    const float* bv    = (const float*)d_in[6];
    const float* gamma = (const float*)d_in[7];
    float* out = (float*)d_out;

    cudaFuncSetAttribute(qkv_kernel, cudaFuncAttributeMaxDynamicSharedMemorySize, Q_SMEM);
    cudaFuncSetAttribute(attn_kernel, cudaFuncAttributeMaxDynamicSharedMemorySize, A_SMEM);

    qkv_kernel<<<dim3(NTOK / 256, 5, BATCH), 256, Q_SMEM>>>(x, Wq, bq, Wk, bk, Wv, bv);
    attn_kernel<<<dim3(NTOK / 128, BATCH), 512, A_SMEM>>>(x, gamma, out);
}